// round 2
// baseline (speedup 1.0000x reference)
#include <cuda_runtime.h>
#include <math.h>
#include <float.h>

#define BATCH 8
#define NPTS  4096
#define KN    10
#define NNB   9
#define PI_F  3.14159265358979323846f
#define INF_F __int_as_float(0x7f800000)

// scratch
__device__ int    g_knn_idx[BATCH * NPTS * NNB];
__device__ float4 g_sorted[BATCH * NPTS];     // sorted by z: {x,y,z, 0.5*|p|^2}
__device__ int    g_sortedIdx[BATCH * NPTS];  // sorted rank -> original index

// ---------------------------------------------------------------------------
// Kernel A: per-batch bitonic sort by z. One block per batch.
// ---------------------------------------------------------------------------
__global__ void __launch_bounds__(512) sortz_kernel(const float* __restrict__ x)
{
    __shared__ float kz[NPTS];
    __shared__ int   ki[NPTS];
    const int b = blockIdx.x;
    const float* xb = x + b * 3 * NPTS;
    const int tid = threadIdx.x;

    for (int i = tid; i < NPTS; i += 512) { kz[i] = xb[2 * NPTS + i]; ki[i] = i; }
    __syncthreads();

    for (int k = 2; k <= NPTS; k <<= 1) {
        for (int j = k >> 1; j > 0; j >>= 1) {
            for (int t = tid; t < NPTS; t += 512) {
                int p = t ^ j;
                if (p > t) {
                    bool up = ((t & k) == 0);
                    float za = kz[t], zb = kz[p];
                    bool sw = up ? (za > zb) : (za < zb);
                    if (sw) {
                        kz[t] = zb; kz[p] = za;
                        int ia = ki[t]; ki[t] = ki[p]; ki[p] = ia;
                    }
                }
            }
            __syncthreads();
        }
    }

    for (int i = tid; i < NPTS; i += 512) {
        int oi = ki[i];
        float px = xb[oi], py = xb[NPTS + oi], pz = xb[2 * NPTS + oi];
        float hs = 0.5f * (px * px + py * py + pz * pz);
        g_sorted[b * NPTS + i] = make_float4(px, py, pz, hs);
        g_sortedIdx[b * NPTS + i] = oi;
    }
}

// ---------------------------------------------------------------------------
// Kernel B: exact kNN via sorted-z two-pointer window scan.
// 1 thread per query (in sorted order). d >= dz^2 lower bound prunes.
// Selection key e = 0.5|p|^2 - q.p  (affine in d: d = 2e + |q|^2, same order).
// ---------------------------------------------------------------------------
__global__ void __launch_bounds__(128) knn2_kernel()
{
    extern __shared__ float4 spt[];   // 4096 sorted points of this batch

    const int gw   = blockIdx.x * 4 + (threadIdx.x >> 5);  // global warp id
    const int lane = threadIdx.x & 31;
    const int batch = gw >> 7;        // 128 warps per batch
    const int wp    = gw & 127;
    const int slab  = ((wp & 7) << 4) + (wp >> 3);  // spread slabs across blocks
    const int r     = slab * 32 + lane;             // sorted rank = my query

    const float4* gb = g_sorted + batch * NPTS;
    for (int i = threadIdx.x; i < NPTS; i += 128) spt[i] = gb[i];
    __syncthreads();

    const float4 q = spt[r];
    const float nqx = -q.x, nqy = -q.y, nqz = -q.z;

    float bd[KN];
    int   brk[KN];
#pragma unroll
    for (int s = 0; s < KN; ++s) { bd[s] = INF_F; brk[s] = 0; }

    int lo = r, hi = r + 1;
    float dzlo = 0.0f;  // self first
    float dzhi = (hi < NPTS) ? spt[hi].z - q.z : INF_F;

#pragma unroll 1
    for (int it = 0; it < NPTS; ++it) {
        bool useLo = (dzlo <= dzhi);
        float dz = useLo ? dzlo : dzhi;
        int   c  = useLo ? lo : hi;

        // lower bound in e-space: e >= 0.5*dz^2 - 0.5*|q|^2
        float bound = fmaf(0.5f * dz, dz, -q.w);
        if (bound > bd[KN - 1] + 1e-5f) break;  // both sides pruned (dz is the min side)

        float4 p = spt[c];
        float e = fmaf(nqx, p.x, fmaf(nqy, p.y, fmaf(nqz, p.z, p.w)));
        if (e < bd[KN - 1]) {
            bd[KN - 1] = e; brk[KN - 1] = c;
#pragma unroll
            for (int s = KN - 1; s >= 1; --s) {
                if (bd[s] < bd[s - 1]) {
                    float td = bd[s]; bd[s] = bd[s - 1]; bd[s - 1] = td;
                    int   ti = brk[s]; brk[s] = brk[s - 1]; brk[s - 1] = ti;
                } else break;
            }
        }

        if (useLo) { --lo; dzlo = (lo >= 0)   ? q.z - spt[lo].z : INF_F; }
        else       { ++hi; dzhi = (hi < NPTS) ? spt[hi].z - q.z : INF_F; }
    }

    // positions 1..9 (drop nearest = self), map sorted rank -> original index
    const int* sidx = g_sortedIdx + batch * NPTS;
    const int orig_q = sidx[r];
    int* outp = g_knn_idx + (batch * NPTS + orig_q) * NNB;
#pragma unroll
    for (int o = 1; o < KN; ++o) outp[o - 1] = sidx[brk[o]];
}

// ---------------------------------------------------------------------------
// Kernel 2: umbrella features + fused MLP (unchanged from passing version)
// ---------------------------------------------------------------------------
__global__ void __launch_bounds__(256) feat_kernel(
    const float* __restrict__ x,
    const float* __restrict__ conv1_w,
    const float* __restrict__ bn1_g, const float* __restrict__ bn1_b,
    const float* __restrict__ bn1_m, const float* __restrict__ bn1_v,
    const float* __restrict__ conv2_w, const float* __restrict__ conv2_b,
    const float* __restrict__ bn2_g, const float* __restrict__ bn2_b,
    const float* __restrict__ bn2_m, const float* __restrict__ bn2_v,
    const float* __restrict__ conv3_w, const float* __restrict__ conv3_b,
    float* __restrict__ out)
{
    extern __shared__ float4 spts[];
    __shared__ float W1f[81], W2f[81], W3s[81];
    __shared__ float b1f[9], b2f[9], b3f[9];

    const int b  = blockIdx.x >> 4;
    const int n0 = (blockIdx.x & 15) * 256;
    const int tid = threadIdx.x;

    if (tid < 81) {
        int o = tid / 9;
        float i1 = bn1_g[o] * rsqrtf(bn1_v[o] + 1e-5f);
        float i2 = bn2_g[o] * rsqrtf(bn2_v[o] + 1e-5f);
        W1f[tid] = conv1_w[tid] * i1;
        W2f[tid] = conv2_w[tid] * i2;
        W3s[tid] = conv3_w[tid];
        if (tid < 9) {
            float j1 = bn1_g[tid] * rsqrtf(bn1_v[tid] + 1e-5f);
            float j2 = bn2_g[tid] * rsqrtf(bn2_v[tid] + 1e-5f);
            b1f[tid] = bn1_b[tid] - bn1_m[tid] * j1;
            b2f[tid] = conv2_b[tid] * j2 + bn2_b[tid] - bn2_m[tid] * j2;
            b3f[tid] = conv3_b[tid];
        }
    }

    const float* xb = x + b * 3 * NPTS;
    for (int i = tid; i < NPTS; i += blockDim.x) {
        spts[i] = make_float4(xb[i], xb[NPTS + i], xb[2 * NPTS + i], 0.0f);
    }
    __syncthreads();

    const int n = n0 + tid;
    float4 p = spts[n];

    float gx[NNB], gy[NNB], gz[NNB], ph[NNB];
    const int* nb = g_knn_idx + (b * NPTS + n) * NNB;
#pragma unroll
    for (int j = 0; j < NNB; ++j) {
        float4 pp = spts[nb[j]];
        gx[j] = pp.x - p.x;
        gy[j] = pp.y - p.y;
        gz[j] = pp.z - p.z;
        ph[j] = atan2f(gy[j], gx[j]);
    }

#pragma unroll 1
    for (int a = 1; a < NNB; ++a) {
        float kp = ph[a], kx = gx[a], ky = gy[a], kz = gz[a];
        int t = a - 1;
        while (t >= 0 && ph[t] > kp) {
            ph[t + 1] = ph[t]; gx[t + 1] = gx[t]; gy[t + 1] = gy[t]; gz[t + 1] = gz[t];
            --t;
        }
        ph[t + 1] = kp; gx[t + 1] = kx; gy[t + 1] = ky; gz[t + 1] = kz;
    }

    float acc[9];
#pragma unroll
    for (int o = 0; o < 9; ++o) acc[o] = 0.0f;

    float pos = 1.0f;

#pragma unroll 1
    for (int j = 0; j < NNB; ++j) {
        int jn = (j + 1 == NNB) ? 0 : j + 1;
        float sx = gx[j],  sy = gy[j],  sz = gz[j];
        float rx = gx[jn], ry = gy[jn], rz = gz[jn];

        float cxv = sy * rz - sz * ry;
        float cyv = sz * rx - sx * rz;
        float czv = sx * ry - sy * rx;
        float nrm = sqrtf(cxv * cxv + cyv * cyv + czv * czv);
        float inn = 1.0f / fmaxf(nrm, 1e-10f);
        float ux = cxv * inn, uy = cyv * inn, uz = czv * inn;
        if (j == 0) pos = (ux > 0.0f) ? 1.0f : -1.0f;
        float nx = ux * pos, ny = uy * pos, nz = uz * pos;
        nx = isnan(nx) ? 0.0f : nx;
        ny = isnan(ny) ? 0.0f : ny;
        nz = isnan(nz) ? 0.0f : nz;

        float ccx = (sx + rx) * (1.0f / 3.0f);
        float ccy = (sy + ry) * (1.0f / 3.0f);
        float ccz = (sz + rz) * (1.0f / 3.0f);
        float rho = sqrtf(ccx * ccx + ccy * ccy + ccz * ccz);
        float ct  = ccz / fmaxf(rho, 1e-8f);
        ct = fminf(fmaxf(ct, -1.0f), 1.0f);
        float th  = acosf(ct) * (1.0f / PI_F);
        float phc = atan2f(ccy, ccx) * (1.0f / (2.0f * PI_F)) + 0.5f;

        float f[9] = { ccx, ccy, ccz, rho, th, phc, nx, ny, nz };

        float h1v[9];
#pragma unroll
        for (int o = 0; o < 9; ++o) {
            float a = b1f[o];
#pragma unroll
            for (int c = 0; c < 9; ++c) a = fmaf(W1f[o * 9 + c], f[c], a);
            h1v[o] = fmaxf(a, 0.0f);
        }
        float h2v[9];
#pragma unroll
        for (int o = 0; o < 9; ++o) {
            float a = b2f[o];
#pragma unroll
            for (int c = 0; c < 9; ++c) a = fmaf(W2f[o * 9 + c], h1v[c], a);
            h2v[o] = fmaxf(a, 0.0f);
        }
#pragma unroll
        for (int o = 0; o < 9; ++o) {
            float a = b3f[o];
#pragma unroll
            for (int c = 0; c < 9; ++c) a = fmaf(W3s[o * 9 + c], h2v[c], a);
            acc[o] += a;
        }
    }

    float* ob = out + b * 9 * NPTS + n;
#pragma unroll
    for (int o = 0; o < 9; ++o) ob[o * NPTS] = acc[o];
}

// ---------------------------------------------------------------------------
extern "C" void kernel_launch(void* const* d_in, const int* in_sizes, int n_in,
                              void* d_out, int out_size)
{
    const float* x       = (const float*)d_in[0];
    const float* conv1_w = (const float*)d_in[1];
    const float* bn1_g   = (const float*)d_in[2];
    const float* bn1_b   = (const float*)d_in[3];
    const float* bn1_m   = (const float*)d_in[4];
    const float* bn1_v   = (const float*)d_in[5];
    const float* conv2_w = (const float*)d_in[6];
    const float* conv2_b = (const float*)d_in[7];
    const float* bn2_g   = (const float*)d_in[8];
    const float* bn2_b   = (const float*)d_in[9];
    const float* bn2_m   = (const float*)d_in[10];
    const float* bn2_v   = (const float*)d_in[11];
    const float* conv3_w = (const float*)d_in[12];
    const float* conv3_b = (const float*)d_in[13];
    float* out = (float*)d_out;

    const int smem = NPTS * (int)sizeof(float4);   // 64 KB
    cudaFuncSetAttribute(knn2_kernel, cudaFuncAttributeMaxDynamicSharedMemorySize, smem);
    cudaFuncSetAttribute(feat_kernel, cudaFuncAttributeMaxDynamicSharedMemorySize, smem);

    sortz_kernel<<<BATCH, 512>>>(x);
    knn2_kernel<<<BATCH * (NPTS / 128), 128, smem>>>();
    feat_kernel<<<BATCH * (NPTS / 256), 256, smem>>>(
        x, conv1_w, bn1_g, bn1_b, bn1_m, bn1_v,
        conv2_w, conv2_b, bn2_g, bn2_b, bn2_m, bn2_v,
        conv3_w, conv3_b, out);
}

// round 3
// speedup vs baseline: 1.7124x; 1.7124x over previous
#include <cuda_runtime.h>
#include <math.h>
#include <float.h>

#define BATCH 8
#define NPTS  4096
#define KN    10
#define NNB   9
#define PI_F  3.14159265358979323846f
#define INF_F __int_as_float(0x7f800000)

// scratch: neighbor indices (B, N, 9)
__device__ int g_knn_idx[BATCH * NPTS * NNB];

// ---------------------------------------------------------------------------
// Kernel 1: brute-force kNN. One thread per query, full 4096-candidate scan.
// All lanes of a warp read the same candidate (broadcast LDS, conflict-free).
// Stable top-10 (strict <, ascending index scan) == lax.top_k ordering.
// ---------------------------------------------------------------------------
__global__ void __launch_bounds__(256) knn_kernel(const float* __restrict__ x)
{
    extern __shared__ float4 spt[];   // 4096 points: {x,y,z, 0.5*|p|^2}

    const int b = blockIdx.x >> 4;            // 16 blocks per batch
    const int q = ((blockIdx.x & 15) << 8) + threadIdx.x;
    const float* xb = x + b * 3 * NPTS;

    for (int i = threadIdx.x; i < NPTS; i += 256) {
        float px = xb[i];
        float py = xb[NPTS + i];
        float pz = xb[2 * NPTS + i];
        spt[i] = make_float4(px, py, pz, 0.5f * (px * px + py * py + pz * pz));
    }
    __syncthreads();

    const float4 qp = spt[q];
    const float nqx = -qp.x, nqy = -qp.y, nqz = -qp.z;

    // selection key: e = 0.5|p|^2 - q.p   (d = 2e + |q|^2, same ordering)
    float bd[KN];
    int   bi[KN];
#pragma unroll
    for (int s = 0; s < KN; ++s) { bd[s] = INF_F; bi[s] = 0x7fffffff; }

#pragma unroll 4
    for (int c = 0; c < NPTS; ++c) {
        float4 p = spt[c];
        float e = fmaf(nqx, p.x, fmaf(nqy, p.y, fmaf(nqz, p.z, p.w)));
        if (e < bd[KN - 1]) {
            bd[KN - 1] = e; bi[KN - 1] = c;
#pragma unroll
            for (int s = KN - 1; s >= 1; --s) {
                if (bd[s] < bd[s - 1]) {   // strict: stable (lower idx first on ties)
                    float td = bd[s]; bd[s] = bd[s - 1]; bd[s - 1] = td;
                    int   ti = bi[s]; bi[s] = bi[s - 1]; bi[s - 1] = ti;
                } else break;
            }
        }
    }

    // nearest is self (or lower-index duplicate) -> drop slot 0, keep 1..9
    int* outp = g_knn_idx + (b * NPTS + q) * NNB;
#pragma unroll
    for (int o = 1; o < KN; ++o) outp[o - 1] = bi[o];
}

// ---------------------------------------------------------------------------
// Kernel 2: umbrella features + fused MLP (BN folded). One thread per (b,n).
// ---------------------------------------------------------------------------
__global__ void __launch_bounds__(256) feat_kernel(
    const float* __restrict__ x,
    const float* __restrict__ conv1_w,
    const float* __restrict__ bn1_g, const float* __restrict__ bn1_b,
    const float* __restrict__ bn1_m, const float* __restrict__ bn1_v,
    const float* __restrict__ conv2_w, const float* __restrict__ conv2_b,
    const float* __restrict__ bn2_g, const float* __restrict__ bn2_b,
    const float* __restrict__ bn2_m, const float* __restrict__ bn2_v,
    const float* __restrict__ conv3_w, const float* __restrict__ conv3_b,
    float* __restrict__ out)
{
    extern __shared__ float4 spts[];
    __shared__ float W1f[81], W2f[81], W3s[81];
    __shared__ float b1f[9], b2f[9], b3f[9];

    const int b  = blockIdx.x >> 4;
    const int n0 = (blockIdx.x & 15) * 256;
    const int tid = threadIdx.x;

    if (tid < 81) {
        int o = tid / 9;
        float i1 = bn1_g[o] * rsqrtf(bn1_v[o] + 1e-5f);
        float i2 = bn2_g[o] * rsqrtf(bn2_v[o] + 1e-5f);
        W1f[tid] = conv1_w[tid] * i1;
        W2f[tid] = conv2_w[tid] * i2;
        W3s[tid] = conv3_w[tid];
        if (tid < 9) {
            float j1 = bn1_g[tid] * rsqrtf(bn1_v[tid] + 1e-5f);
            float j2 = bn2_g[tid] * rsqrtf(bn2_v[tid] + 1e-5f);
            b1f[tid] = bn1_b[tid] - bn1_m[tid] * j1;
            b2f[tid] = conv2_b[tid] * j2 + bn2_b[tid] - bn2_m[tid] * j2;
            b3f[tid] = conv3_b[tid];
        }
    }

    const float* xb = x + b * 3 * NPTS;
    for (int i = tid; i < NPTS; i += blockDim.x) {
        spts[i] = make_float4(xb[i], xb[NPTS + i], xb[2 * NPTS + i], 0.0f);
    }
    __syncthreads();

    const int n = n0 + tid;
    float4 p = spts[n];

    float gx[NNB], gy[NNB], gz[NNB], ph[NNB];
    const int* nb = g_knn_idx + (b * NPTS + n) * NNB;
#pragma unroll
    for (int j = 0; j < NNB; ++j) {
        float4 pp = spts[nb[j]];
        gx[j] = pp.x - p.x;
        gy[j] = pp.y - p.y;
        gz[j] = pp.z - p.z;
        ph[j] = atan2f(gy[j], gx[j]);
    }

#pragma unroll 1
    for (int a = 1; a < NNB; ++a) {
        float kp = ph[a], kx = gx[a], ky = gy[a], kz = gz[a];
        int t = a - 1;
        while (t >= 0 && ph[t] > kp) {
            ph[t + 1] = ph[t]; gx[t + 1] = gx[t]; gy[t + 1] = gy[t]; gz[t + 1] = gz[t];
            --t;
        }
        ph[t + 1] = kp; gx[t + 1] = kx; gy[t + 1] = ky; gz[t + 1] = kz;
    }

    float acc[9];
#pragma unroll
    for (int o = 0; o < 9; ++o) acc[o] = 0.0f;

    float pos = 1.0f;

#pragma unroll 1
    for (int j = 0; j < NNB; ++j) {
        int jn = (j + 1 == NNB) ? 0 : j + 1;
        float sx = gx[j],  sy = gy[j],  sz = gz[j];
        float rx = gx[jn], ry = gy[jn], rz = gz[jn];

        float cxv = sy * rz - sz * ry;
        float cyv = sz * rx - sx * rz;
        float czv = sx * ry - sy * rx;
        float nrm = sqrtf(cxv * cxv + cyv * cyv + czv * czv);
        float inn = 1.0f / fmaxf(nrm, 1e-10f);
        float ux = cxv * inn, uy = cyv * inn, uz = czv * inn;
        if (j == 0) pos = (ux > 0.0f) ? 1.0f : -1.0f;
        float nx = ux * pos, ny = uy * pos, nz = uz * pos;
        nx = isnan(nx) ? 0.0f : nx;
        ny = isnan(ny) ? 0.0f : ny;
        nz = isnan(nz) ? 0.0f : nz;

        float ccx = (sx + rx) * (1.0f / 3.0f);
        float ccy = (sy + ry) * (1.0f / 3.0f);
        float ccz = (sz + rz) * (1.0f / 3.0f);
        float rho = sqrtf(ccx * ccx + ccy * ccy + ccz * ccz);
        float ct  = ccz / fmaxf(rho, 1e-8f);
        ct = fminf(fmaxf(ct, -1.0f), 1.0f);
        float th  = acosf(ct) * (1.0f / PI_F);
        float phc = atan2f(ccy, ccx) * (1.0f / (2.0f * PI_F)) + 0.5f;

        float f[9] = { ccx, ccy, ccz, rho, th, phc, nx, ny, nz };

        float h1v[9];
#pragma unroll
        for (int o = 0; o < 9; ++o) {
            float a = b1f[o];
#pragma unroll
            for (int c = 0; c < 9; ++c) a = fmaf(W1f[o * 9 + c], f[c], a);
            h1v[o] = fmaxf(a, 0.0f);
        }
        float h2v[9];
#pragma unroll
        for (int o = 0; o < 9; ++o) {
            float a = b2f[o];
#pragma unroll
            for (int c = 0; c < 9; ++c) a = fmaf(W2f[o * 9 + c], h1v[c], a);
            h2v[o] = fmaxf(a, 0.0f);
        }
#pragma unroll
        for (int o = 0; o < 9; ++o) {
            float a = b3f[o];
#pragma unroll
            for (int c = 0; c < 9; ++c) a = fmaf(W3s[o * 9 + c], h2v[c], a);
            acc[o] += a;
        }
    }

    float* ob = out + b * 9 * NPTS + n;
#pragma unroll
    for (int o = 0; o < 9; ++o) ob[o * NPTS] = acc[o];
}

// ---------------------------------------------------------------------------
extern "C" void kernel_launch(void* const* d_in, const int* in_sizes, int n_in,
                              void* d_out, int out_size)
{
    const float* x       = (const float*)d_in[0];
    const float* conv1_w = (const float*)d_in[1];
    const float* bn1_g   = (const float*)d_in[2];
    const float* bn1_b   = (const float*)d_in[3];
    const float* bn1_m   = (const float*)d_in[4];
    const float* bn1_v   = (const float*)d_in[5];
    const float* conv2_w = (const float*)d_in[6];
    const float* conv2_b = (const float*)d_in[7];
    const float* bn2_g   = (const float*)d_in[8];
    const float* bn2_b   = (const float*)d_in[9];
    const float* bn2_m   = (const float*)d_in[10];
    const float* bn2_v   = (const float*)d_in[11];
    const float* conv3_w = (const float*)d_in[12];
    const float* conv3_b = (const float*)d_in[13];
    float* out = (float*)d_out;

    const int smem = NPTS * (int)sizeof(float4);   // 64 KB
    cudaFuncSetAttribute(knn_kernel,  cudaFuncAttributeMaxDynamicSharedMemorySize, smem);
    cudaFuncSetAttribute(feat_kernel, cudaFuncAttributeMaxDynamicSharedMemorySize, smem);

    knn_kernel<<<BATCH * (NPTS / 256), 256, smem>>>(x);
    feat_kernel<<<BATCH * (NPTS / 256), 256, smem>>>(
        x, conv1_w, bn1_g, bn1_b, bn1_m, bn1_v,
        conv2_w, conv2_b, bn2_g, bn2_b, bn2_m, bn2_v,
        conv3_w, conv3_b, out);
}

// round 4
// speedup vs baseline: 2.3440x; 1.3689x over previous
#include <cuda_runtime.h>
#include <math.h>
#include <float.h>

#define BATCH 8
#define NPTS  4096
#define KN    10
#define NNB   9
#define PI_F  3.14159265358979323846f
#define INF_F __int_as_float(0x7f800000)

// scratch: neighbor indices (B, N, 9)
__device__ int g_knn_idx[BATCH * NPTS * NNB];

// ---------------------------------------------------------------------------
// Kernel 1: brute-force kNN. One thread per query, full 4096-candidate scan.
// Unsorted top-10 with running max: replace-max insert (no serial swap chain).
// Output = set of 9 nearest excluding self (order irrelevant downstream).
// ---------------------------------------------------------------------------
__global__ void __launch_bounds__(256) knn_kernel(const float* __restrict__ x)
{
    extern __shared__ float4 spt[];   // 4096 points: {x,y,z, 0.5*|p|^2}

    const int b = blockIdx.x >> 4;            // 16 blocks per batch
    const int q = ((blockIdx.x & 15) << 8) + threadIdx.x;
    const float* xb = x + b * 3 * NPTS;

    for (int i = threadIdx.x; i < NPTS; i += 256) {
        float px = xb[i];
        float py = xb[NPTS + i];
        float pz = xb[2 * NPTS + i];
        spt[i] = make_float4(px, py, pz, 0.5f * (px * px + py * py + pz * pz));
    }
    __syncthreads();

    const float4 qp = spt[q];
    const float nqx = -qp.x, nqy = -qp.y, nqz = -qp.z;

    // selection key: e = 0.5|p|^2 - q.p   (monotone with d, exact set match)
    float bd[KN];
    int   bi[KN];

    // warmup: first 10 candidates fill the slots branch-free
#pragma unroll
    for (int s = 0; s < KN; ++s) {
        float4 p = spt[s];
        bd[s] = fmaf(nqx, p.x, fmaf(nqy, p.y, fmaf(nqz, p.z, p.w)));
        bi[s] = s;
    }
    float mx = bd[0];
#pragma unroll
    for (int s = 1; s < KN; ++s) mx = fmaxf(mx, bd[s]);

#pragma unroll 4
    for (int c = KN; c < NPTS; ++c) {
        float4 p = spt[c];
        float e = fmaf(nqx, p.x, fmaf(nqy, p.y, fmaf(nqz, p.z, p.w)));
        if (e < mx) {
            // replace the first slot holding mx
            bool rep = false;
#pragma unroll
            for (int s = 0; s < KN; ++s) {
                bool m = (!rep) && (bd[s] == mx);
                if (m) { bd[s] = e; bi[s] = c; }
                rep = rep || m;
            }
            // recompute running max (tree)
            float m0 = fmaxf(bd[0], bd[1]);
            float m1 = fmaxf(bd[2], bd[3]);
            float m2 = fmaxf(bd[4], bd[5]);
            float m3 = fmaxf(bd[6], bd[7]);
            float m4 = fmaxf(bd[8], bd[9]);
            mx = fmaxf(fmaxf(fmaxf(m0, m1), fmaxf(m2, m3)), m4);
        }
    }

    // self = strict min; emit the other 9 (order arbitrary)
    float mn = bd[0]; int ms = 0;
#pragma unroll
    for (int s = 1; s < KN; ++s) {
        if (bd[s] < mn) { mn = bd[s]; ms = s; }
    }

    int* outp = g_knn_idx + (b * NPTS + q) * NNB;
    int k = 0;
#pragma unroll
    for (int s = 0; s < KN; ++s) {
        if (s != ms) { outp[k] = bi[s]; ++k; }
    }
}

// ---------------------------------------------------------------------------
// Kernel 2: umbrella features + fused MLP (BN folded). One thread per (b,n).
// ---------------------------------------------------------------------------
__global__ void __launch_bounds__(256) feat_kernel(
    const float* __restrict__ x,
    const float* __restrict__ conv1_w,
    const float* __restrict__ bn1_g, const float* __restrict__ bn1_b,
    const float* __restrict__ bn1_m, const float* __restrict__ bn1_v,
    const float* __restrict__ conv2_w, const float* __restrict__ conv2_b,
    const float* __restrict__ bn2_g, const float* __restrict__ bn2_b,
    const float* __restrict__ bn2_m, const float* __restrict__ bn2_v,
    const float* __restrict__ conv3_w, const float* __restrict__ conv3_b,
    float* __restrict__ out)
{
    extern __shared__ float4 spts[];
    __shared__ float W1f[81], W2f[81], W3s[81];
    __shared__ float b1f[9], b2f[9], b3f[9];

    const int b  = blockIdx.x >> 4;
    const int n0 = (blockIdx.x & 15) * 256;
    const int tid = threadIdx.x;

    if (tid < 81) {
        int o = tid / 9;
        float i1 = bn1_g[o] * rsqrtf(bn1_v[o] + 1e-5f);
        float i2 = bn2_g[o] * rsqrtf(bn2_v[o] + 1e-5f);
        W1f[tid] = conv1_w[tid] * i1;
        W2f[tid] = conv2_w[tid] * i2;
        W3s[tid] = conv3_w[tid];
        if (tid < 9) {
            float j1 = bn1_g[tid] * rsqrtf(bn1_v[tid] + 1e-5f);
            float j2 = bn2_g[tid] * rsqrtf(bn2_v[tid] + 1e-5f);
            b1f[tid] = bn1_b[tid] - bn1_m[tid] * j1;
            b2f[tid] = conv2_b[tid] * j2 + bn2_b[tid] - bn2_m[tid] * j2;
            b3f[tid] = conv3_b[tid];
        }
    }

    const float* xb = x + b * 3 * NPTS;
    for (int i = tid; i < NPTS; i += blockDim.x) {
        spts[i] = make_float4(xb[i], xb[NPTS + i], xb[2 * NPTS + i], 0.0f);
    }
    __syncthreads();

    const int n = n0 + tid;
    float4 p = spts[n];

    float gx[NNB], gy[NNB], gz[NNB], ph[NNB];
    const int* nb = g_knn_idx + (b * NPTS + n) * NNB;
#pragma unroll
    for (int j = 0; j < NNB; ++j) {
        float4 pp = spts[nb[j]];
        gx[j] = pp.x - p.x;
        gy[j] = pp.y - p.y;
        gz[j] = pp.z - p.z;
        ph[j] = atan2f(gy[j], gx[j]);
    }

#pragma unroll 1
    for (int a = 1; a < NNB; ++a) {
        float kp = ph[a], kx = gx[a], ky = gy[a], kz = gz[a];
        int t = a - 1;
        while (t >= 0 && ph[t] > kp) {
            ph[t + 1] = ph[t]; gx[t + 1] = gx[t]; gy[t + 1] = gy[t]; gz[t + 1] = gz[t];
            --t;
        }
        ph[t + 1] = kp; gx[t + 1] = kx; gy[t + 1] = ky; gz[t + 1] = kz;
    }

    float acc[9];
#pragma unroll
    for (int o = 0; o < 9; ++o) acc[o] = 0.0f;

    float pos = 1.0f;

#pragma unroll 1
    for (int j = 0; j < NNB; ++j) {
        int jn = (j + 1 == NNB) ? 0 : j + 1;
        float sx = gx[j],  sy = gy[j],  sz = gz[j];
        float rx = gx[jn], ry = gy[jn], rz = gz[jn];

        float cxv = sy * rz - sz * ry;
        float cyv = sz * rx - sx * rz;
        float czv = sx * ry - sy * rx;
        float nrm = sqrtf(cxv * cxv + cyv * cyv + czv * czv);
        float inn = 1.0f / fmaxf(nrm, 1e-10f);
        float ux = cxv * inn, uy = cyv * inn, uz = czv * inn;
        if (j == 0) pos = (ux > 0.0f) ? 1.0f : -1.0f;
        float nx = ux * pos, ny = uy * pos, nz = uz * pos;
        nx = isnan(nx) ? 0.0f : nx;
        ny = isnan(ny) ? 0.0f : ny;
        nz = isnan(nz) ? 0.0f : nz;

        float ccx = (sx + rx) * (1.0f / 3.0f);
        float ccy = (sy + ry) * (1.0f / 3.0f);
        float ccz = (sz + rz) * (1.0f / 3.0f);
        float rho = sqrtf(ccx * ccx + ccy * ccy + ccz * ccz);
        float ct  = ccz / fmaxf(rho, 1e-8f);
        ct = fminf(fmaxf(ct, -1.0f), 1.0f);
        float th  = acosf(ct) * (1.0f / PI_F);
        float phc = atan2f(ccy, ccx) * (1.0f / (2.0f * PI_F)) + 0.5f;

        float f[9] = { ccx, ccy, ccz, rho, th, phc, nx, ny, nz };

        float h1v[9];
#pragma unroll
        for (int o = 0; o < 9; ++o) {
            float a = b1f[o];
#pragma unroll
            for (int c = 0; c < 9; ++c) a = fmaf(W1f[o * 9 + c], f[c], a);
            h1v[o] = fmaxf(a, 0.0f);
        }
        float h2v[9];
#pragma unroll
        for (int o = 0; o < 9; ++o) {
            float a = b2f[o];
#pragma unroll
            for (int c = 0; c < 9; ++c) a = fmaf(W2f[o * 9 + c], h1v[c], a);
            h2v[o] = fmaxf(a, 0.0f);
        }
#pragma unroll
        for (int o = 0; o < 9; ++o) {
            float a = b3f[o];
#pragma unroll
            for (int c = 0; c < 9; ++c) a = fmaf(W3s[o * 9 + c], h2v[c], a);
            acc[o] += a;
        }
    }

    float* ob = out + b * 9 * NPTS + n;
#pragma unroll
    for (int o = 0; o < 9; ++o) ob[o * NPTS] = acc[o];
}

// ---------------------------------------------------------------------------
extern "C" void kernel_launch(void* const* d_in, const int* in_sizes, int n_in,
                              void* d_out, int out_size)
{
    const float* x       = (const float*)d_in[0];
    const float* conv1_w = (const float*)d_in[1];
    const float* bn1_g   = (const float*)d_in[2];
    const float* bn1_b   = (const float*)d_in[3];
    const float* bn1_m   = (const float*)d_in[4];
    const float* bn1_v   = (const float*)d_in[5];
    const float* conv2_w = (const float*)d_in[6];
    const float* conv2_b = (const float*)d_in[7];
    const float* bn2_g   = (const float*)d_in[8];
    const float* bn2_b   = (const float*)d_in[9];
    const float* bn2_m   = (const float*)d_in[10];
    const float* bn2_v   = (const float*)d_in[11];
    const float* conv3_w = (const float*)d_in[12];
    const float* conv3_b = (const float*)d_in[13];
    float* out = (float*)d_out;

    const int smem = NPTS * (int)sizeof(float4);   // 64 KB
    cudaFuncSetAttribute(knn_kernel,  cudaFuncAttributeMaxDynamicSharedMemorySize, smem);
    cudaFuncSetAttribute(feat_kernel, cudaFuncAttributeMaxDynamicSharedMemorySize, smem);

    knn_kernel<<<BATCH * (NPTS / 256), 256, smem>>>(x);
    feat_kernel<<<BATCH * (NPTS / 256), 256, smem>>>(
        x, conv1_w, bn1_g, bn1_b, bn1_m, bn1_v,
        conv2_w, conv2_b, bn2_g, bn2_b, bn2_m, bn2_v,
        conv3_w, conv3_b, out);
}

// round 5
// speedup vs baseline: 2.8344x; 1.2092x over previous
#include <cuda_runtime.h>
#include <math.h>
#include <float.h>

#define BATCH 8
#define NPTS  4096
#define KN    10
#define NNB   9
#define PI_F  3.14159265358979323846f
#define INF_F __int_as_float(0x7f800000)

// scratch: neighbor indices (B, N, 9)
__device__ int g_knn_idx[BATCH * NPTS * NNB];

// ---------------------------------------------------------------------------
// insert helper: unsorted top-10 with running max (parallel predicated form)
// ---------------------------------------------------------------------------
#define KNN_INSERT(e, c)                                                     \
    if ((e) < mx) {                                                          \
        bool rep = false;                                                    \
        _Pragma("unroll")                                                    \
        for (int s = 0; s < KN; ++s) {                                       \
            bool m = (!rep) && (bd[s] == mx);                                \
            if (m) { bd[s] = (e); bi[s] = (c); }                             \
            rep = rep || m;                                                  \
        }                                                                    \
        float m0 = fmaxf(bd[0], bd[1]);                                      \
        float m1 = fmaxf(bd[2], bd[3]);                                      \
        float m2 = fmaxf(bd[4], bd[5]);                                      \
        float m3 = fmaxf(bd[6], bd[7]);                                      \
        float m4 = fmaxf(bd[8], bd[9]);                                      \
        mx = fmaxf(fmaxf(fmaxf(m0, m1), fmaxf(m2, m3)), m4);                 \
    }

// ---------------------------------------------------------------------------
// Kernel 1: brute-force kNN. 2 threads per query (2048 candidates each),
// 512-thread blocks (16 warps/SM). Grouped 4-candidate branch on min(e)<mx.
// Exact merge of the two partial top-10s in SMEM, drop self (= global min).
// ---------------------------------------------------------------------------
__global__ void __launch_bounds__(512) knn_kernel(const float* __restrict__ x)
{
    extern __shared__ float4 spt[];   // 4096 points: {x,y,z, 0.5*|p|^2}

    const int b  = blockIdx.x >> 4;           // 16 blocks per batch
    const int q0 = (blockIdx.x & 15) << 8;    // 256 queries per block
    const float* xb = x + b * 3 * NPTS;
    const int tid = threadIdx.x;

    for (int i = tid; i < NPTS; i += 512) {
        float px = xb[i];
        float py = xb[NPTS + i];
        float pz = xb[2 * NPTS + i];
        spt[i] = make_float4(px, py, pz, 0.5f * (px * px + py * py + pz * pz));
    }
    __syncthreads();

    const int sub = tid >> 8;        // warps 0-7: sub 0, warps 8-15: sub 1
    const int ql  = tid & 255;
    const int q   = q0 + ql;
    const int c0  = sub * (NPTS / 2);

    const float4 qp = spt[q];
    const float nqx = -qp.x, nqy = -qp.y, nqz = -qp.z;

    float bd[KN];
    int   bi[KN];

    // warmup: first 12 candidates (10 fill + 2 singles so the rest is /4)
#pragma unroll
    for (int s = 0; s < KN; ++s) {
        float4 p = spt[c0 + s];
        bd[s] = fmaf(nqx, p.x, fmaf(nqy, p.y, fmaf(nqz, p.z, p.w)));
        bi[s] = c0 + s;
    }
    float mx = bd[0];
#pragma unroll
    for (int s = 1; s < KN; ++s) mx = fmaxf(mx, bd[s]);
    {
        float4 pa = spt[c0 + KN];
        float4 pb = spt[c0 + KN + 1];
        float ea = fmaf(nqx, pa.x, fmaf(nqy, pa.y, fmaf(nqz, pa.z, pa.w)));
        float eb = fmaf(nqx, pb.x, fmaf(nqy, pb.y, fmaf(nqz, pb.z, pb.w)));
        KNN_INSERT(ea, c0 + KN);
        KNN_INSERT(eb, c0 + KN + 1);
    }

#pragma unroll 2
    for (int c = c0 + KN + 2; c < c0 + NPTS / 2; c += 4) {
        float4 p0 = spt[c];
        float4 p1 = spt[c + 1];
        float4 p2 = spt[c + 2];
        float4 p3 = spt[c + 3];
        float e0 = fmaf(nqx, p0.x, fmaf(nqy, p0.y, fmaf(nqz, p0.z, p0.w)));
        float e1 = fmaf(nqx, p1.x, fmaf(nqy, p1.y, fmaf(nqz, p1.z, p1.w)));
        float e2 = fmaf(nqx, p2.x, fmaf(nqy, p2.y, fmaf(nqz, p2.z, p2.w)));
        float e3 = fmaf(nqx, p3.x, fmaf(nqy, p3.y, fmaf(nqz, p3.z, p3.w)));
        float em = fminf(fminf(e0, e1), fminf(e2, e3));
        if (em < mx) {
            KNN_INSERT(e0, c);
            KNN_INSERT(e1, c + 1);
            KNN_INSERT(e2, c + 2);
            KNN_INSERT(e3, c + 3);
        }
    }

    // --- exact merge of the two partial lists (reuse SMEM) ---
    __syncthreads();
    float* pd = (float*)spt;                    // 512*10 floats = 20 KB
    int*   pi = (int*)(pd + 512 * KN);          // 512*10 ints   = 20 KB

    const int base = (ql * 2 + sub) * KN;
#pragma unroll
    for (int s = 0; s < KN; ++s) { pd[base + s] = bd[s]; pi[base + s] = bi[s]; }
    __syncthreads();

    if (sub == 0) {
        // slots already hold this thread's own partial (sub 0); insert sub 1's.
        const int ob = (ql * 2 + 1) * KN;
#pragma unroll
        for (int s = 0; s < KN; ++s) {
            float e = pd[ob + s];
            int   c = pi[ob + s];
            KNN_INSERT(e, c);
        }

        // self = strict global min; emit the other 9 (order arbitrary)
        float mn = bd[0]; int ms = 0;
#pragma unroll
        for (int s = 1; s < KN; ++s) {
            if (bd[s] < mn) { mn = bd[s]; ms = s; }
        }
        int* outp = g_knn_idx + (b * NPTS + q) * NNB;
        int k = 0;
#pragma unroll
        for (int s = 0; s < KN; ++s) {
            if (s != ms) { outp[k] = bi[s]; ++k; }
        }
    }
}

// ---------------------------------------------------------------------------
// Kernel 2: umbrella features + fused MLP (BN folded). One thread per (b,n).
// ---------------------------------------------------------------------------
__global__ void __launch_bounds__(256) feat_kernel(
    const float* __restrict__ x,
    const float* __restrict__ conv1_w,
    const float* __restrict__ bn1_g, const float* __restrict__ bn1_b,
    const float* __restrict__ bn1_m, const float* __restrict__ bn1_v,
    const float* __restrict__ conv2_w, const float* __restrict__ conv2_b,
    const float* __restrict__ bn2_g, const float* __restrict__ bn2_b,
    const float* __restrict__ bn2_m, const float* __restrict__ bn2_v,
    const float* __restrict__ conv3_w, const float* __restrict__ conv3_b,
    float* __restrict__ out)
{
    extern __shared__ float4 spts[];
    __shared__ float W1f[81], W2f[81], W3s[81];
    __shared__ float b1f[9], b2f[9], b3f[9];

    const int b  = blockIdx.x >> 4;
    const int n0 = (blockIdx.x & 15) * 256;
    const int tid = threadIdx.x;

    if (tid < 81) {
        int o = tid / 9;
        float i1 = bn1_g[o] * rsqrtf(bn1_v[o] + 1e-5f);
        float i2 = bn2_g[o] * rsqrtf(bn2_v[o] + 1e-5f);
        W1f[tid] = conv1_w[tid] * i1;
        W2f[tid] = conv2_w[tid] * i2;
        W3s[tid] = conv3_w[tid];
        if (tid < 9) {
            float j1 = bn1_g[tid] * rsqrtf(bn1_v[tid] + 1e-5f);
            float j2 = bn2_g[tid] * rsqrtf(bn2_v[tid] + 1e-5f);
            b1f[tid] = bn1_b[tid] - bn1_m[tid] * j1;
            b2f[tid] = conv2_b[tid] * j2 + bn2_b[tid] - bn2_m[tid] * j2;
            b3f[tid] = conv3_b[tid];
        }
    }

    const float* xb = x + b * 3 * NPTS;
    for (int i = tid; i < NPTS; i += blockDim.x) {
        spts[i] = make_float4(xb[i], xb[NPTS + i], xb[2 * NPTS + i], 0.0f);
    }
    __syncthreads();

    const int n = n0 + tid;
    float4 p = spts[n];

    float gx[NNB], gy[NNB], gz[NNB], ph[NNB];
    const int* nb = g_knn_idx + (b * NPTS + n) * NNB;
#pragma unroll
    for (int j = 0; j < NNB; ++j) {
        float4 pp = spts[nb[j]];
        gx[j] = pp.x - p.x;
        gy[j] = pp.y - p.y;
        gz[j] = pp.z - p.z;
        ph[j] = atan2f(gy[j], gx[j]);
    }

#pragma unroll 1
    for (int a = 1; a < NNB; ++a) {
        float kp = ph[a], kx = gx[a], ky = gy[a], kz = gz[a];
        int t = a - 1;
        while (t >= 0 && ph[t] > kp) {
            ph[t + 1] = ph[t]; gx[t + 1] = gx[t]; gy[t + 1] = gy[t]; gz[t + 1] = gz[t];
            --t;
        }
        ph[t + 1] = kp; gx[t + 1] = kx; gy[t + 1] = ky; gz[t + 1] = kz;
    }

    float acc[9];
#pragma unroll
    for (int o = 0; o < 9; ++o) acc[o] = 0.0f;

    float pos = 1.0f;

#pragma unroll 1
    for (int j = 0; j < NNB; ++j) {
        int jn = (j + 1 == NNB) ? 0 : j + 1;
        float sx = gx[j],  sy = gy[j],  sz = gz[j];
        float rx = gx[jn], ry = gy[jn], rz = gz[jn];

        float cxv = sy * rz - sz * ry;
        float cyv = sz * rx - sx * rz;
        float czv = sx * ry - sy * rx;
        float nrm = sqrtf(cxv * cxv + cyv * cyv + czv * czv);
        float inn = 1.0f / fmaxf(nrm, 1e-10f);
        float ux = cxv * inn, uy = cyv * inn, uz = czv * inn;
        if (j == 0) pos = (ux > 0.0f) ? 1.0f : -1.0f;
        float nx = ux * pos, ny = uy * pos, nz = uz * pos;
        nx = isnan(nx) ? 0.0f : nx;
        ny = isnan(ny) ? 0.0f : ny;
        nz = isnan(nz) ? 0.0f : nz;

        float ccx = (sx + rx) * (1.0f / 3.0f);
        float ccy = (sy + ry) * (1.0f / 3.0f);
        float ccz = (sz + rz) * (1.0f / 3.0f);
        float rho = sqrtf(ccx * ccx + ccy * ccy + ccz * ccz);
        float ct  = ccz / fmaxf(rho, 1e-8f);
        ct = fminf(fmaxf(ct, -1.0f), 1.0f);
        float th  = acosf(ct) * (1.0f / PI_F);
        float phc = atan2f(ccy, ccx) * (1.0f / (2.0f * PI_F)) + 0.5f;

        float f[9] = { ccx, ccy, ccz, rho, th, phc, nx, ny, nz };

        float h1v[9];
#pragma unroll
        for (int o = 0; o < 9; ++o) {
            float a = b1f[o];
#pragma unroll
            for (int c = 0; c < 9; ++c) a = fmaf(W1f[o * 9 + c], f[c], a);
            h1v[o] = fmaxf(a, 0.0f);
        }
        float h2v[9];
#pragma unroll
        for (int o = 0; o < 9; ++o) {
            float a = b2f[o];
#pragma unroll
            for (int c = 0; c < 9; ++c) a = fmaf(W2f[o * 9 + c], h1v[c], a);
            h2v[o] = fmaxf(a, 0.0f);
        }
#pragma unroll
        for (int o = 0; o < 9; ++o) {
            float a = b3f[o];
#pragma unroll
            for (int c = 0; c < 9; ++c) a = fmaf(W3s[o * 9 + c], h2v[c], a);
            acc[o] += a;
        }
    }

    float* ob = out + b * 9 * NPTS + n;
#pragma unroll
    for (int o = 0; o < 9; ++o) ob[o * NPTS] = acc[o];
}

// ---------------------------------------------------------------------------
extern "C" void kernel_launch(void* const* d_in, const int* in_sizes, int n_in,
                              void* d_out, int out_size)
{
    const float* x       = (const float*)d_in[0];
    const float* conv1_w = (const float*)d_in[1];
    const float* bn1_g   = (const float*)d_in[2];
    const float* bn1_b   = (const float*)d_in[3];
    const float* bn1_m   = (const float*)d_in[4];
    const float* bn1_v   = (const float*)d_in[5];
    const float* conv2_w = (const float*)d_in[6];
    const float* conv2_b = (const float*)d_in[7];
    const float* bn2_g   = (const float*)d_in[8];
    const float* bn2_b   = (const float*)d_in[9];
    const float* bn2_m   = (const float*)d_in[10];
    const float* bn2_v   = (const float*)d_in[11];
    const float* conv3_w = (const float*)d_in[12];
    const float* conv3_b = (const float*)d_in[13];
    float* out = (float*)d_out;

    const int smem = NPTS * (int)sizeof(float4);   // 64 KB
    cudaFuncSetAttribute(knn_kernel,  cudaFuncAttributeMaxDynamicSharedMemorySize, smem);
    cudaFuncSetAttribute(feat_kernel, cudaFuncAttributeMaxDynamicSharedMemorySize, smem);

    knn_kernel<<<BATCH * (NPTS / 256), 512, smem>>>(x);
    feat_kernel<<<BATCH * (NPTS / 256), 256, smem>>>(
        x, conv1_w, bn1_g, bn1_b, bn1_m, bn1_v,
        conv2_w, conv2_b, bn2_g, bn2_b, bn2_m, bn2_v,
        conv3_w, conv3_b, out);
}